// round 16
// baseline (speedup 1.0000x reference)
#include <cuda_runtime.h>
#include <cuda_fp16.h>
#include <cstdint>

#define HW      65536
#define NPIX    524288
#define THREADS 512
#define PX_CTA  512
#define NCTAS   (NPIX / PX_CTA)   // 1024

// ---- dynamic smem byte layout ----
#define SW_OFF  0          // float2[341] pair-packed w3..w7 = 2728 -> pad 2752
#define B1_OFF  2752       // w1 fp16 (single): 64*272 = 17408 -> ends 20160
#define B2_OFF  20160      // w2 fp16 (single): 32*144 = 4608  -> ends 24768
#define STG_OFF 24768      // A staging: 16 warps * 2KB = 32KB (overlaps EX; mainloop only)
#define EX_OFF  24768      // a1 exchange [c2][px]: 16 * 512 * 8 = 65536 -> ends 90304
#define SMEM_TOTAL 90304

#define B1_PITCH 272
#define B2_PITCH 144

// pair-packed weight offsets inside s_w (float2 units)
#define W3OFF 0            // 32c x 8  = 256
#define W4OFF 256          // 16c x 4  = 64
#define W5OFF 320          // 8c  x 2  = 16
#define W6OFF 336          // 4c  x 1  = 4
#define W7OFF 340

__device__ __forceinline__ uint32_t smem_u32(const void* p) {
    uint32_t a;
    asm("{ .reg .u64 t; cvta.to.shared.u64 t, %1; cvt.u32.u64 %0, t; }" : "=r"(a) : "l"(p));
    return a;
}
__device__ __forceinline__ float2 ffma2(float2 a, float2 b, float2 c) {
    unsigned long long ra = reinterpret_cast<unsigned long long&>(a);
    unsigned long long rb = reinterpret_cast<unsigned long long&>(b);
    unsigned long long rc = reinterpret_cast<unsigned long long&>(c);
    unsigned long long rd;
    asm("fma.rn.f32x2 %0, %1, %2, %3;" : "=l"(rd) : "l"(ra), "l"(rb), "l"(rc));
    return reinterpret_cast<float2&>(rd);
}
__device__ __forceinline__ float2 leaky2(float2 v) {
    v.x = fmaxf(v.x, 0.01f * v.x);
    v.y = fmaxf(v.y, 0.01f * v.y);
    return v;
}
__device__ __forceinline__ void ldmx4(uint32_t* r, uint32_t addr) {
    asm volatile("ldmatrix.sync.aligned.m8n8.x4.shared.b16 {%0,%1,%2,%3}, [%4];"
                 : "=r"(r[0]), "=r"(r[1]), "=r"(r[2]), "=r"(r[3]) : "r"(addr));
}
// fp16 MMA: D(f32) += A(f16) * B(f16)
__device__ __forceinline__ void mma16816(float* d, const uint32_t* a, uint32_t b0, uint32_t b1) {
    asm volatile("mma.sync.aligned.m16n8k16.row.col.f32.f16.f16.f32 "
                 "{%0,%1,%2,%3}, {%4,%5,%6,%7}, {%8,%9}, {%0,%1,%2,%3};"
                 : "+f"(d[0]), "+f"(d[1]), "+f"(d[2]), "+f"(d[3])
                 : "r"(a[0]), "r"(a[1]), "r"(a[2]), "r"(a[3]), "r"(b0), "r"(b1));
}

// fp16 A-split: hi = f32 truncated to 10 mantissa bits (exact under F2FP pack),
// lo = RN(f - hi). Per pair: 2 LOP3 + 2 FADD + 2 F2FP.
__device__ __forceinline__ void cvt_hilo(float f0, float f1, uint32_t& hi, uint32_t& lo) {
    float h0 = __uint_as_float(__float_as_uint(f0) & 0xFFFFE000u);
    float h1 = __uint_as_float(__float_as_uint(f1) & 0xFFFFE000u);
    __half2 hh = __floats2half2_rn(h0, h1);          // exact pack
    __half2 ll = __floats2half2_rn(f0 - h0, f1 - h1);
    hi = reinterpret_cast<uint32_t&>(hh);
    lo = reinterpret_cast<uint32_t&>(ll);
}

__device__ __forceinline__ void stage_pairs(float2* dst, const float* __restrict__ w,
                                            int cout, int cin, int tid) {
    int npair = (cout / 2) * cin;
    for (int i = tid; i < npair; i += THREADS) {
        int o2 = i / cin;
        int c  = i - o2 * cin;
        dst[c * (cout / 2) + o2] = make_float2(w[(2 * o2) * cin + c], w[(2 * o2 + 1) * cin + c]);
    }
}

// stage weight [cout][cin] as SINGLE fp16 RN rows
__device__ __forceinline__ void stage_fp16(char* base, uint32_t pitch,
                                           const float* __restrict__ w, int cout, int cin, int tid) {
    for (int i = tid; i < cout * cin; i += THREADS) {
        int o = i / cin, c = i - o * cin;
        __half h = __float2half_rn(w[i]);
        *reinterpret_cast<uint16_t*>(base + o * pitch + c * 2) = reinterpret_cast<uint16_t&>(h);
    }
}

// Scalar layer for ONE pixel, channel-pair packed.
template <int CIN, int COUT>
__device__ __forceinline__ void layerv(const float2* __restrict__ sw, const float2* in, float2* outv) {
    constexpr int O2 = COUT / 2;
#pragma unroll
    for (int o = 0; o < O2; ++o) outv[o] = make_float2(0.f, 0.f);
#pragma unroll
    for (int c2 = 0; c2 < CIN / 2; ++c2) {
        float2 v = in[c2];
#pragma unroll
        for (int h = 0; h < 2; ++h) {
            float s = h ? v.y : v.x;
            float2 d = make_float2(s, s);
            const float2* wr = sw + (2 * c2 + h) * O2;
            if constexpr ((O2 & 1) == 0) {
                const float4* w4 = reinterpret_cast<const float4*>(wr);
#pragma unroll
                for (int o4 = 0; o4 < O2 / 2; ++o4) {
                    float4 wp = w4[o4];
                    outv[2 * o4]     = ffma2(d, make_float2(wp.x, wp.y), outv[2 * o4]);
                    outv[2 * o4 + 1] = ffma2(d, make_float2(wp.z, wp.w), outv[2 * o4 + 1]);
                }
            } else {
#pragma unroll
                for (int o = 0; o < O2; ++o) outv[o] = ffma2(d, wr[o], outv[o]);
            }
        }
    }
}

__global__ __launch_bounds__(THREADS, 1)
void fused_mlp7_hmma6_kernel(const float* __restrict__ x,
                             const float* __restrict__ w1, const float* __restrict__ w2,
                             const float* __restrict__ w3, const float* __restrict__ w4,
                             const float* __restrict__ w5, const float* __restrict__ w6,
                             const float* __restrict__ w7,
                             float* __restrict__ out) {
    extern __shared__ char sm[];
    float2* s_w   = reinterpret_cast<float2*>(sm + SW_OFF);
    float2* ex_f2 = reinterpret_cast<float2*>(sm + EX_OFF);

    const int tid  = threadIdx.x;
    const int lane = tid & 31;
    const int warp = tid >> 5;          // 0..15

    const uint32_t smu = smem_u32(sm);
    const uint32_t B1h = smu + B1_OFF;
    const uint32_t B2h = smu + B2_OFF;
    const uint32_t ws  = smu + STG_OFF + warp * 2048;   // hi plane; lo at +1024

    stage_fp16(sm + B1_OFF, B1_PITCH, w1, 64, 128, tid);
    stage_fp16(sm + B2_OFF, B2_PITCH, w2, 32, 64, tid);
    stage_pairs(s_w + W3OFF, w3, 16, 32, tid);
    stage_pairs(s_w + W4OFF, w4, 8, 16, tid);
    stage_pairs(s_w + W5OFF, w5, 4, 8, tid);
    stage_pairs(s_w + W6OFF, w6, 2, 4, tid);
    if (tid == 0) s_w[W7OFF] = make_float2(w7[0], w7[1]);
    __syncthreads();

    // ---- this CTA's 512-px slab (always within one image) ----
    const int slab = blockIdx.x * PX_CTA;
    const float* xb = x + (size_t)(slab >> 16) * (128 * HW) + (slab & (HW - 1));

    const int pxw  = warp * 32;                         // warp's 32-px tile
    const int lrow = (lane & 7) + ((lane >> 3) & 1) * 8;
    const int lchk = lane >> 4;

    // STS swizzled offsets (lane = px): c16_phys = c16 ^ ((px>>2)&1)
    const uint32_t s_swz = ((lane >> 2) & 1) * 16;
    const uint32_t so0 = (uint32_t)lane * 32 + s_swz;          // c0-7 chunk
    const uint32_t so1 = so0 ^ 16;                              // c8-15 chunk

    // ldmatrix A addresses (two mb tiles), swizzle applied per row
    uint32_t a_off[2];
#pragma unroll
    for (int mb = 0; mb < 2; ++mb) {
        uint32_t arow = (uint32_t)(mb * 16 + lrow);
        a_off[mb] = arow * 32 + ((uint32_t)(lchk ^ ((arow >> 2) & 1)) * 16);
    }

    // ================= Layer 1: MMA 32px x 64o x K128, 2 chains =================
    float acc[2][8][4];
#pragma unroll
    for (int mb = 0; mb < 2; ++mb)
#pragma unroll
        for (int nb = 0; nb < 8; ++nb)
#pragma unroll
            for (int r = 0; r < 4; ++r) acc[mb][nb][r] = 0.f;

    float xf[16];
#define LOAD_XF(kb_)                                                              \
    do {                                                                          \
        const float* cbk = xb + (size_t)(kb_) * 16 * HW + pxw;                    \
        _Pragma("unroll")                                                         \
        for (int i = 0; i < 16; ++i) xf[i] = cbk[(size_t)i * HW + lane];          \
    } while (0)

    LOAD_XF(0);

#pragma unroll
    for (int kb = 0; kb < 8; ++kb) {
        // convert current (px-major: lane = px, 16 channels)
        uint32_t h2[8], l2[8];
#pragma unroll
        for (int j = 0; j < 8; ++j)
            cvt_hilo(xf[2 * j], xf[2 * j + 1], h2[j], l2[j]);
        if (kb < 7) LOAD_XF(kb + 1);    // prefetch next k-step

        __syncwarp();                    // prior ldmatrix reads done before overwrite
        asm volatile("st.shared.v4.b32 [%0], {%1,%2,%3,%4};" ::
                     "r"(ws + so0), "r"(h2[0]), "r"(h2[1]), "r"(h2[2]), "r"(h2[3]) : "memory");
        asm volatile("st.shared.v4.b32 [%0], {%1,%2,%3,%4};" ::
                     "r"(ws + so1), "r"(h2[4]), "r"(h2[5]), "r"(h2[6]), "r"(h2[7]) : "memory");
        asm volatile("st.shared.v4.b32 [%0], {%1,%2,%3,%4};" ::
                     "r"(ws + 1024 + so0), "r"(l2[0]), "r"(l2[1]), "r"(l2[2]), "r"(l2[3]) : "memory");
        asm volatile("st.shared.v4.b32 [%0], {%1,%2,%3,%4};" ::
                     "r"(ws + 1024 + so1), "r"(l2[4]), "r"(l2[5]), "r"(l2[6]), "r"(l2[7]) : "memory");
        __syncwarp();

        uint32_t AH[2][4], AL[2][4];
#pragma unroll
        for (int mb = 0; mb < 2; ++mb) {
            ldmx4(AH[mb], ws + a_off[mb]);
            ldmx4(AL[mb], ws + 1024 + a_off[mb]);
        }

#pragma unroll
        for (int p = 0; p < 4; ++p) {
            uint32_t BHf[4];
            uint32_t bd = B1h + (uint32_t)(p * 16 + lrow) * B1_PITCH + kb * 32 + lchk * 16;
            ldmx4(BHf, bd);
#pragma unroll
            for (int mb = 0; mb < 2; ++mb) {
                mma16816(acc[mb][2 * p],     AH[mb], BHf[0], BHf[2]);
                mma16816(acc[mb][2 * p + 1], AH[mb], BHf[1], BHf[3]);
            }
#pragma unroll
            for (int mb = 0; mb < 2; ++mb) {
                mma16816(acc[mb][2 * p],     AL[mb], BHf[0], BHf[2]);
                mma16816(acc[mb][2 * p + 1], AL[mb], BHf[1], BHf[3]);
            }
        }
    }
#undef LOAD_XF

    // ================= Layer 2: MMA 32px x 32o x K64, A from D fragments, 2 chains =================
    float acc2[2][4][4];
#pragma unroll
    for (int mb = 0; mb < 2; ++mb)
#pragma unroll
        for (int nb = 0; nb < 4; ++nb)
#pragma unroll
            for (int r = 0; r < 4; ++r) acc2[mb][nb][r] = 0.f;

#pragma unroll
    for (int kb2 = 0; kb2 < 4; ++kb2) {
        uint32_t A2H[2][4], A2L[2][4];
#pragma unroll
        for (int mb = 0; mb < 2; ++mb) {
            float2 v0 = leaky2(make_float2(acc[mb][2 * kb2][0],     acc[mb][2 * kb2][1]));
            float2 v1 = leaky2(make_float2(acc[mb][2 * kb2][2],     acc[mb][2 * kb2][3]));
            float2 v2 = leaky2(make_float2(acc[mb][2 * kb2 + 1][0], acc[mb][2 * kb2 + 1][1]));
            float2 v3 = leaky2(make_float2(acc[mb][2 * kb2 + 1][2], acc[mb][2 * kb2 + 1][3]));
            cvt_hilo(v0.x, v0.y, A2H[mb][0], A2L[mb][0]);
            cvt_hilo(v1.x, v1.y, A2H[mb][1], A2L[mb][1]);
            cvt_hilo(v2.x, v2.y, A2H[mb][2], A2L[mb][2]);
            cvt_hilo(v3.x, v3.y, A2H[mb][3], A2L[mb][3]);
        }
#pragma unroll
        for (int p2 = 0; p2 < 2; ++p2) {
            uint32_t BHf[4];
            uint32_t bd = B2h + (uint32_t)(p2 * 16 + lrow) * B2_PITCH + kb2 * 32 + lchk * 16;
            ldmx4(BHf, bd);
#pragma unroll
            for (int mb = 0; mb < 2; ++mb) {
                mma16816(acc2[mb][2 * p2],     A2H[mb], BHf[0], BHf[2]);
                mma16816(acc2[mb][2 * p2 + 1], A2H[mb], BHf[1], BHf[3]);
            }
#pragma unroll
            for (int mb = 0; mb < 2; ++mb) {
                mma16816(acc2[mb][2 * p2],     A2L[mb], BHf[0], BHf[2]);
                mma16816(acc2[mb][2 * p2 + 1], A2L[mb], BHf[1], BHf[3]);
            }
        }
    }

    // ---- all warps done with staging region before exchange overwrites it ----
    __syncthreads();

    // ---- a1 = leaky(acc2) -> exchange [c2][px] (conflict-free float2) ----
    {
        const int qr = lane >> 2, qc = lane & 3;
#pragma unroll
        for (int mb = 0; mb < 2; ++mb) {
            int px0 = pxw + mb * 16 + qr;
#pragma unroll
            for (int nb = 0; nb < 4; ++nb) {
                int c2 = nb * 4 + qc;
                ex_f2[c2 * 512 + px0]     = leaky2(make_float2(acc2[mb][nb][0], acc2[mb][nb][1]));
                ex_f2[c2 * 512 + px0 + 8] = leaky2(make_float2(acc2[mb][nb][2], acc2[mb][nb][3]));
            }
        }
    }
    __syncthreads();

    // ================= Layers 3..7: scalar, 1 px/thread =================
    float2 a1[16];
#pragma unroll
    for (int c2 = 0; c2 < 16; ++c2) a1[c2] = ex_f2[c2 * 512 + tid];

    float2 a2[8];
    layerv<32, 16>(s_w + W3OFF, a1, a2);
#pragma unroll
    for (int o = 0; o < 8; ++o) a2[o] = leaky2(a2[o]);
    float2 a3[4];
    layerv<16, 8>(s_w + W4OFF, a2, a3);
#pragma unroll
    for (int o = 0; o < 4; ++o) a3[o] = leaky2(a3[o]);
    float2 a4[2];
    layerv<8, 4>(s_w + W5OFF, a3, a4);
#pragma unroll
    for (int o = 0; o < 2; ++o) a4[o] = leaky2(a4[o]);
    float2 a5[1];
    layerv<4, 2>(s_w + W6OFF, a4, a5);
    a5[0] = leaky2(a5[0]);

    float2 w7p = s_w[W7OFF];
    out[slab + tid] = fmaf(a5[0].x, w7p.x, a5[0].y * w7p.y);
}

extern "C" void kernel_launch(void* const* d_in, const int* in_sizes, int n_in,
                              void* d_out, int out_size) {
    const float* x  = (const float*)d_in[0];
    const float* w1 = (const float*)d_in[1];
    const float* w2 = (const float*)d_in[2];
    const float* w3 = (const float*)d_in[3];
    const float* w4 = (const float*)d_in[4];
    const float* w5 = (const float*)d_in[5];
    const float* w6 = (const float*)d_in[6];
    const float* w7 = (const float*)d_in[7];
    float* out = (float*)d_out;

    cudaFuncSetAttribute(fused_mlp7_hmma6_kernel,
                         cudaFuncAttributeMaxDynamicSharedMemorySize, SMEM_TOTAL);
    fused_mlp7_hmma6_kernel<<<NCTAS, THREADS, SMEM_TOTAL>>>(x, w1, w2, w3, w4, w5, w6, w7, out);
}

// round 17
// speedup vs baseline: 1.0653x; 1.0653x over previous
#include <cuda_runtime.h>
#include <cuda_fp16.h>
#include <cstdint>

#define HW      65536
#define NPIX    524288
#define THREADS 512
#define PX_CTA  512
#define NCTAS   (NPIX / PX_CTA)   // 1024

// ---- dynamic smem byte layout ----
#define SW_OFF  0          // float2[341] pair-packed w3..w7 = 2728 -> pad 2752
#define B1_OFF  2752       // w1 fp16 (single): 64*272 = 17408 -> ends 20160
#define B2_OFF  20160      // w2 fp16 (single): 32*144 = 4608  -> ends 24768
#define EX_OFF  24768      // a1 exchange [c2][px]: 16 * 512 * 8 = 65536 -> ends 90304
#define SMEM_TOTAL 90304

#define B1_PITCH 272
#define B2_PITCH 144

// pair-packed weight offsets inside s_w (float2 units)
#define W3OFF 0            // 32c x 8  = 256
#define W4OFF 256          // 16c x 4  = 64
#define W5OFF 320          // 8c  x 2  = 16
#define W6OFF 336          // 4c  x 1  = 4
#define W7OFF 340

__device__ __forceinline__ uint32_t smem_u32(const void* p) {
    uint32_t a;
    asm("{ .reg .u64 t; cvta.to.shared.u64 t, %1; cvt.u32.u64 %0, t; }" : "=r"(a) : "l"(p));
    return a;
}
__device__ __forceinline__ float2 ffma2(float2 a, float2 b, float2 c) {
    unsigned long long ra = reinterpret_cast<unsigned long long&>(a);
    unsigned long long rb = reinterpret_cast<unsigned long long&>(b);
    unsigned long long rc = reinterpret_cast<unsigned long long&>(c);
    unsigned long long rd;
    asm("fma.rn.f32x2 %0, %1, %2, %3;" : "=l"(rd) : "l"(ra), "l"(rb), "l"(rc));
    return reinterpret_cast<float2&>(rd);
}
__device__ __forceinline__ float2 leaky2(float2 v) {
    v.x = fmaxf(v.x, 0.01f * v.x);
    v.y = fmaxf(v.y, 0.01f * v.y);
    return v;
}
__device__ __forceinline__ void ldmx4(uint32_t* r, uint32_t addr) {
    asm volatile("ldmatrix.sync.aligned.m8n8.x4.shared.b16 {%0,%1,%2,%3}, [%4];"
                 : "=r"(r[0]), "=r"(r[1]), "=r"(r[2]), "=r"(r[3]) : "r"(addr));
}
// fp16 MMA: D(f32) += A(f16) * B(f16)
__device__ __forceinline__ void mma16816(float* d, const uint32_t* a, uint32_t b0, uint32_t b1) {
    asm volatile("mma.sync.aligned.m16n8k16.row.col.f32.f16.f16.f32 "
                 "{%0,%1,%2,%3}, {%4,%5,%6,%7}, {%8,%9}, {%0,%1,%2,%3};"
                 : "+f"(d[0]), "+f"(d[1]), "+f"(d[2]), "+f"(d[3])
                 : "r"(a[0]), "r"(a[1]), "r"(a[2]), "r"(a[3]), "r"(b0), "r"(b1));
}

// fp16 A-split: hi = f32 truncated to 10 mantissa bits (exact under F2FP pack),
// lo = RN(f - hi).
__device__ __forceinline__ void cvt_hilo(float f0, float f1, uint32_t& hi, uint32_t& lo) {
    float h0 = __uint_as_float(__float_as_uint(f0) & 0xFFFFE000u);
    float h1 = __uint_as_float(__float_as_uint(f1) & 0xFFFFE000u);
    __half2 hh = __floats2half2_rn(h0, h1);          // exact pack
    __half2 ll = __floats2half2_rn(f0 - h0, f1 - h1);
    hi = reinterpret_cast<uint32_t&>(hh);
    lo = reinterpret_cast<uint32_t&>(ll);
}

__device__ __forceinline__ void stage_pairs(float2* dst, const float* __restrict__ w,
                                            int cout, int cin, int tid) {
    int npair = (cout / 2) * cin;
    for (int i = tid; i < npair; i += THREADS) {
        int o2 = i / cin;
        int c  = i - o2 * cin;
        dst[c * (cout / 2) + o2] = make_float2(w[(2 * o2) * cin + c], w[(2 * o2 + 1) * cin + c]);
    }
}

// stage weight [cout][cin] as SINGLE fp16 RN rows
__device__ __forceinline__ void stage_fp16(char* base, uint32_t pitch,
                                           const float* __restrict__ w, int cout, int cin, int tid) {
    for (int i = tid; i < cout * cin; i += THREADS) {
        int o = i / cin, c = i - o * cin;
        __half h = __float2half_rn(w[i]);
        *reinterpret_cast<uint16_t*>(base + o * pitch + c * 2) = reinterpret_cast<uint16_t&>(h);
    }
}

// Scalar layer for ONE pixel, channel-pair packed.
template <int CIN, int COUT>
__device__ __forceinline__ void layerv(const float2* __restrict__ sw, const float2* in, float2* outv) {
    constexpr int O2 = COUT / 2;
#pragma unroll
    for (int o = 0; o < O2; ++o) outv[o] = make_float2(0.f, 0.f);
#pragma unroll
    for (int c2 = 0; c2 < CIN / 2; ++c2) {
        float2 v = in[c2];
#pragma unroll
        for (int h = 0; h < 2; ++h) {
            float s = h ? v.y : v.x;
            float2 d = make_float2(s, s);
            const float2* wr = sw + (2 * c2 + h) * O2;
            if constexpr ((O2 & 1) == 0) {
                const float4* w4 = reinterpret_cast<const float4*>(wr);
#pragma unroll
                for (int o4 = 0; o4 < O2 / 2; ++o4) {
                    float4 wp = w4[o4];
                    outv[2 * o4]     = ffma2(d, make_float2(wp.x, wp.y), outv[2 * o4]);
                    outv[2 * o4 + 1] = ffma2(d, make_float2(wp.z, wp.w), outv[2 * o4 + 1]);
                }
            } else {
#pragma unroll
                for (int o = 0; o < O2; ++o) outv[o] = ffma2(d, wr[o], outv[o]);
            }
        }
    }
}

__global__ __launch_bounds__(THREADS, 1)
void fused_mlp7_hmma7_kernel(const float* __restrict__ x,
                             const float* __restrict__ w1, const float* __restrict__ w2,
                             const float* __restrict__ w3, const float* __restrict__ w4,
                             const float* __restrict__ w5, const float* __restrict__ w6,
                             const float* __restrict__ w7,
                             float* __restrict__ out) {
    extern __shared__ char sm[];
    float2* s_w   = reinterpret_cast<float2*>(sm + SW_OFF);
    float2* ex_f2 = reinterpret_cast<float2*>(sm + EX_OFF);

    const int tid  = threadIdx.x;
    const int lane = tid & 31;
    const int warp = tid >> 5;          // 0..15

    const uint32_t smu = smem_u32(sm);
    const uint32_t B1h = smu + B1_OFF;
    const uint32_t B2h = smu + B2_OFF;

    stage_fp16(sm + B1_OFF, B1_PITCH, w1, 64, 128, tid);
    stage_fp16(sm + B2_OFF, B2_PITCH, w2, 32, 64, tid);
    stage_pairs(s_w + W3OFF, w3, 16, 32, tid);
    stage_pairs(s_w + W4OFF, w4, 8, 16, tid);
    stage_pairs(s_w + W5OFF, w5, 4, 8, tid);
    stage_pairs(s_w + W6OFF, w6, 2, 4, tid);
    if (tid == 0) s_w[W7OFF] = make_float2(w7[0], w7[1]);
    __syncthreads();

    // ---- this CTA's 512-px slab (always within one image) ----
    const int slab = blockIdx.x * PX_CTA;
    const float* xb = x + (size_t)(slab >> 16) * (128 * HW) + (slab & (HW - 1));

    const int fg = lane >> 2;          // fragment row group (0..7)
    const int t2 = (lane & 3) * 2;     // fragment col pair base
    const int pxw = warp * 32;         // warp's 32-px tile
    const int lrow = (lane & 7) + ((lane >> 3) & 1) * 8;
    const int lchk = lane >> 4;

    // ================= Layer 1: MMA 32px x 64o x K128, 2 chains =================
    float acc[2][8][4];
#pragma unroll
    for (int mb = 0; mb < 2; ++mb)
#pragma unroll
        for (int nb = 0; nb < 8; ++nb)
#pragma unroll
            for (int r = 0; r < 4; ++r) acc[mb][nb][r] = 0.f;

    // double-buffered x fragments: prefetch distance 2 k-steps (covers DRAM latency)
    float xr[2][2][8];
#define LOAD_XR(buf_, kb_)                                                        \
    do {                                                                          \
        const float* cb0 = xb + (size_t)((kb_) * 16 + t2) * HW;                   \
        const float* cb1 = cb0 + HW;                                              \
        const float* cb8 = cb0 + (size_t)8 * HW;                                  \
        const float* cb9 = cb8 + HW;                                              \
        _Pragma("unroll")                                                         \
        for (int mb = 0; mb < 2; ++mb) {                                          \
            int p0 = pxw + mb * 16 + fg;                                          \
            xr[buf_][mb][0] = cb0[p0];     xr[buf_][mb][1] = cb1[p0];             \
            xr[buf_][mb][2] = cb0[p0 + 8]; xr[buf_][mb][3] = cb1[p0 + 8];         \
            xr[buf_][mb][4] = cb8[p0];     xr[buf_][mb][5] = cb9[p0];             \
            xr[buf_][mb][6] = cb8[p0 + 8]; xr[buf_][mb][7] = cb9[p0 + 8];         \
        }                                                                         \
    } while (0)

    LOAD_XR(0, 0);
    LOAD_XR(1, 1);

#pragma unroll
    for (int kb = 0; kb < 8; ++kb) {
        const int buf = kb & 1;
        uint32_t AH[2][4], AL[2][4];
#pragma unroll
        for (int mb = 0; mb < 2; ++mb) {
            cvt_hilo(xr[buf][mb][0], xr[buf][mb][1], AH[mb][0], AL[mb][0]);
            cvt_hilo(xr[buf][mb][2], xr[buf][mb][3], AH[mb][1], AL[mb][1]);
            cvt_hilo(xr[buf][mb][4], xr[buf][mb][5], AH[mb][2], AL[mb][2]);
            cvt_hilo(xr[buf][mb][6], xr[buf][mb][7], AH[mb][3], AL[mb][3]);
        }
        // prefetch kb+2 into the buffer just consumed (distance 2)
        if (kb < 6) LOAD_XR(buf, kb + 2);

#pragma unroll
        for (int p = 0; p < 4; ++p) {
            uint32_t BHf[4];
            uint32_t bd = B1h + (uint32_t)(p * 16 + lrow) * B1_PITCH + kb * 32 + lchk * 16;
            ldmx4(BHf, bd);
            // 2 chains: AhiB, AloB (chain-major for long acc reuse distance)
#pragma unroll
            for (int mb = 0; mb < 2; ++mb) {
                mma16816(acc[mb][2 * p],     AH[mb], BHf[0], BHf[2]);
                mma16816(acc[mb][2 * p + 1], AH[mb], BHf[1], BHf[3]);
            }
#pragma unroll
            for (int mb = 0; mb < 2; ++mb) {
                mma16816(acc[mb][2 * p],     AL[mb], BHf[0], BHf[2]);
                mma16816(acc[mb][2 * p + 1], AL[mb], BHf[1], BHf[3]);
            }
        }
    }
#undef LOAD_XR

    // ================= Layer 2: MMA 32px x 32o x K64, A from D fragments, 2 chains =================
    float acc2[2][4][4];
#pragma unroll
    for (int mb = 0; mb < 2; ++mb)
#pragma unroll
        for (int nb = 0; nb < 4; ++nb)
#pragma unroll
            for (int r = 0; r < 4; ++r) acc2[mb][nb][r] = 0.f;

#pragma unroll
    for (int kb2 = 0; kb2 < 4; ++kb2) {
        uint32_t A2H[2][4], A2L[2][4];
#pragma unroll
        for (int mb = 0; mb < 2; ++mb) {
            float2 v0 = leaky2(make_float2(acc[mb][2 * kb2][0],     acc[mb][2 * kb2][1]));
            float2 v1 = leaky2(make_float2(acc[mb][2 * kb2][2],     acc[mb][2 * kb2][3]));
            float2 v2 = leaky2(make_float2(acc[mb][2 * kb2 + 1][0], acc[mb][2 * kb2 + 1][1]));
            float2 v3 = leaky2(make_float2(acc[mb][2 * kb2 + 1][2], acc[mb][2 * kb2 + 1][3]));
            cvt_hilo(v0.x, v0.y, A2H[mb][0], A2L[mb][0]);
            cvt_hilo(v1.x, v1.y, A2H[mb][1], A2L[mb][1]);
            cvt_hilo(v2.x, v2.y, A2H[mb][2], A2L[mb][2]);
            cvt_hilo(v3.x, v3.y, A2H[mb][3], A2L[mb][3]);
        }
#pragma unroll
        for (int p2 = 0; p2 < 2; ++p2) {
            uint32_t BHf[4];
            uint32_t bd = B2h + (uint32_t)(p2 * 16 + lrow) * B2_PITCH + kb2 * 32 + lchk * 16;
            ldmx4(BHf, bd);
#pragma unroll
            for (int mb = 0; mb < 2; ++mb) {
                mma16816(acc2[mb][2 * p2],     A2H[mb], BHf[0], BHf[2]);
                mma16816(acc2[mb][2 * p2 + 1], A2H[mb], BHf[1], BHf[3]);
            }
#pragma unroll
            for (int mb = 0; mb < 2; ++mb) {
                mma16816(acc2[mb][2 * p2],     A2L[mb], BHf[0], BHf[2]);
                mma16816(acc2[mb][2 * p2 + 1], A2L[mb], BHf[1], BHf[3]);
            }
        }
    }

    // ---- a1 = leaky(acc2) -> exchange [c2][px] (conflict-free float2) ----
    {
        const int qr = lane >> 2, qc = lane & 3;
#pragma unroll
        for (int mb = 0; mb < 2; ++mb) {
            int px0 = pxw + mb * 16 + qr;
#pragma unroll
            for (int nb = 0; nb < 4; ++nb) {
                int c2 = nb * 4 + qc;
                ex_f2[c2 * 512 + px0]     = leaky2(make_float2(acc2[mb][nb][0], acc2[mb][nb][1]));
                ex_f2[c2 * 512 + px0 + 8] = leaky2(make_float2(acc2[mb][nb][2], acc2[mb][nb][3]));
            }
        }
    }
    __syncthreads();

    // ================= Layers 3..7: scalar, 1 px/thread =================
    float2 a1[16];
#pragma unroll
    for (int c2 = 0; c2 < 16; ++c2) a1[c2] = ex_f2[c2 * 512 + tid];

    float2 a2[8];
    layerv<32, 16>(s_w + W3OFF, a1, a2);
#pragma unroll
    for (int o = 0; o < 8; ++o) a2[o] = leaky2(a2[o]);
    float2 a3[4];
    layerv<16, 8>(s_w + W4OFF, a2, a3);
#pragma unroll
    for (int o = 0; o < 4; ++o) a3[o] = leaky2(a3[o]);
    float2 a4[2];
    layerv<8, 4>(s_w + W5OFF, a3, a4);
#pragma unroll
    for (int o = 0; o < 2; ++o) a4[o] = leaky2(a4[o]);
    float2 a5[1];
    layerv<4, 2>(s_w + W6OFF, a4, a5);
    a5[0] = leaky2(a5[0]);

    float2 w7p = s_w[W7OFF];
    out[slab + tid] = fmaf(a5[0].x, w7p.x, a5[0].y * w7p.y);
}

extern "C" void kernel_launch(void* const* d_in, const int* in_sizes, int n_in,
                              void* d_out, int out_size) {
    const float* x  = (const float*)d_in[0];
    const float* w1 = (const float*)d_in[1];
    const float* w2 = (const float*)d_in[2];
    const float* w3 = (const float*)d_in[3];
    const float* w4 = (const float*)d_in[4];
    const float* w5 = (const float*)d_in[5];
    const float* w6 = (const float*)d_in[6];
    const float* w7 = (const float*)d_in[7];
    float* out = (float*)d_out;

    cudaFuncSetAttribute(fused_mlp7_hmma7_kernel,
                         cudaFuncAttributeMaxDynamicSharedMemorySize, SMEM_TOTAL);
    fused_mlp7_hmma7_kernel<<<NCTAS, THREADS, SMEM_TOTAL>>>(x, w1, w2, w3, w4, w5, w6, w7, out);
}